// round 17
// baseline (speedup 1.0000x reference)
#include <cuda_runtime.h>
#include <cuda_fp16.h>

#define H_IMG 1080
#define W_IMG 1920
#define GY 16
#define GX 16
#define GW 8
#define NPIX (H_IMG * W_IMG)

#define BX 384                      // threads per block
#define PXE 3                       // elements per thread
#define PXB 384                     // pixels per block: 1920 = 5 * 384, no tail
#define NC 5                        // x-cell columns (incl. +1 margin)
#define NCELL (NC * GW)             // 40 cells, 120 slab entries

#define SX (15.0f / 1919.0f)
#define SY (15.0f / 1079.0f)

__device__ __forceinline__ unsigned f2h2(float a, float b) {
    __half2 h = __floats2half2_rn(a, b);
    return *reinterpret_cast<unsigned*>(&h);
}

__global__ __launch_bounds__(BX, 4) void bilateral_grid_kernel(
    const float* __restrict__ rgb,
    const float* __restrict__ grids,
    const int*   __restrict__ idxp,
    float*       __restrict__ out)
{
    __shared__ __align__(16) uint4  slabh[NCELL * 3];   // 120*16 = 1920B
    __shared__ __align__(8)  float2 xtab[PXB];          // 3KB {wx, o0 bits}

    const int tid   = threadIdx.x;
    const int row   = blockIdx.y;
    const int xpix0 = blockIdx.x * PXB;
    const int xbase = (int)((float)xpix0 * SX);

    const int q0 = tid / 3;             // 0..127
    const int c  = tid - 3 * q0;        // 0..2
    const int n0 = row * W_IMG + xpix0 + q0;

    // ---- rgb prefetch: 3 pixels q0, q0+128, q0+256 (all valid) ----
    float rr[PXE], gg[PXE], bb[PXE];
    #pragma unroll
    for (int k = 0; k < PXE; k++) {
        rr[k] = __ldcs(rgb + n0 + k * 128);
        gg[k] = __ldcs(rgb + NPIX + n0 + k * 128);
        bb[k] = __ldcs(rgb + 2 * NPIX + n0 + k * 128);
    }

    if (tid < NCELL * 3) {
        // ---- slab build: y-lerp + z-delta, packed fp16. 120 threads ----
        const float* grid = grids + (size_t)idxp[0] * (GY * GX * GW * 12);
        float gyv = (float)row * SY;
        float fy  = floorf(gyv);
        float wy  = gyv - fy;
        int y0 = min((int)fy, GY - 1);
        int y1 = min(y0 + 1, GY - 1);
        float wy0 = 1.0f - wy, wy1 = wy;

        int cell = tid / 3;
        int c4   = tid - cell * 3;
        int xq   = cell / GW;
        int zq   = cell - xq * GW;
        int zq1  = min(zq + 1, GW - 1);
        int xc   = min(xbase + xq, GX - 1);

        float4 a0 = __ldg(reinterpret_cast<const float4*>(
            grid + ((size_t)(y0 * GX + xc) * GW + zq)  * 12) + c4);
        float4 a1 = __ldg(reinterpret_cast<const float4*>(
            grid + ((size_t)(y1 * GX + xc) * GW + zq)  * 12) + c4);
        float4 bb0 = __ldg(reinterpret_cast<const float4*>(
            grid + ((size_t)(y0 * GX + xc) * GW + zq1) * 12) + c4);
        float4 bb1 = __ldg(reinterpret_cast<const float4*>(
            grid + ((size_t)(y1 * GX + xc) * GW + zq1) * 12) + c4);

        float4 v, nx;
        v.x  = wy0 * a0.x  + wy1 * a1.x;   v.y  = wy0 * a0.y  + wy1 * a1.y;
        v.z  = wy0 * a0.z  + wy1 * a1.z;   v.w  = wy0 * a0.w  + wy1 * a1.w;
        nx.x = wy0 * bb0.x + wy1 * bb1.x;  nx.y = wy0 * bb0.y + wy1 * bb1.y;
        nx.z = wy0 * bb0.z + wy1 * bb1.z;  nx.w = wy0 * bb0.w + wy1 * bb1.w;

        uint4 pk;
        pk.x = f2h2(v.x, v.y);
        pk.y = f2h2(v.z, v.w);
        pk.z = f2h2(nx.x - v.x, nx.y - v.y);
        pk.w = f2h2(nx.z - v.z, nx.w - v.w);
        slabh[tid] = pk;
    }

    // ---- x-table build: all 384 threads, one pass ----
    {
        int x  = xpix0 + tid;
        float gxv = (float)x * SX;
        float fx  = floorf(gxv);
        float wx  = gxv - fx;
        int xc0 = min((int)fx, GX - 1);
        int o0 = (xc0 - xbase) * (GW * 3);
        xtab[tid] = make_float2(wx, __int_as_float(o0));
    }
    __syncthreads();

    const size_t base3 = (size_t)(row * W_IMG + xpix0) * 3;
    float4* aff = reinterpret_cast<float4*>(out) + base3;
    float*  res = out + (size_t)12 * NPIX + base3;

    #pragma unroll
    for (int k = 0; k < PXE; k++) {
        float r = rr[k], g = gg[k], b = bb[k];

        float gray = 0.299f * r + 0.587f * g + 0.114f * b;
        float gz = __saturatef(gray) * 7.0f;
        float fz = floorf(gz);
        float wz = gz - fz;
        int z0 = (int)fz;

        float2 xe = xtab[q0 + k * 128];
        float wx  = xe.x;
        int ia = __float_as_int(xe.y) + z0 * 3 + c;
        uint4 ua = slabh[ia];
        uint4 ub = slabh[ia + GW * 3];

        __half2 wz2 = __float2half2_rn(wz);
        __half2 ta0 = __hfma2(wz2, *(__half2*)&ua.z, *(__half2*)&ua.x);
        __half2 ta1 = __hfma2(wz2, *(__half2*)&ua.w, *(__half2*)&ua.y);
        __half2 tb0 = __hfma2(wz2, *(__half2*)&ub.z, *(__half2*)&ub.x);
        __half2 tb1 = __hfma2(wz2, *(__half2*)&ub.w, *(__half2*)&ub.y);

        float2 fa0 = __half22float2(ta0), fa1 = __half22float2(ta1);
        float2 fb0 = __half22float2(tb0), fb1 = __half22float2(tb1);

        float w0 = 1.0f - wx;
        float4 a4;
        a4.x = fmaf(wx, fb0.x, w0 * fa0.x);
        a4.y = fmaf(wx, fb0.y, w0 * fa0.y);
        a4.z = fmaf(wx, fb1.x, w0 * fa1.x);
        a4.w = fmaf(wx, fb1.y, w0 * fa1.y);

        __stcs(aff + tid + k * BX, a4);
        __stcs(res + tid + k * BX,
               fmaf(a4.x, r, fmaf(a4.y, g, fmaf(a4.z, b, a4.w))));
    }
}

extern "C" void kernel_launch(void* const* d_in, const int* in_sizes, int n_in,
                              void* d_out, int out_size) {
    const float* rgb   = (const float*)d_in[0];
    const float* grids = (const float*)d_in[1];
    const int*   idx   = (const int*)d_in[2];
    float* out = (float*)d_out;

    dim3 grid(W_IMG / PXB, H_IMG);   // 5 x 1080
    bilateral_grid_kernel<<<grid, BX>>>(rgb, grids, idx, out);
}